// round 7
// baseline (speedup 1.0000x reference)
#include <cuda_runtime.h>
#include <math.h>
#include <stdint.h>

#define S_LEN 2048
#define DM    2048
#define QH    32
#define KVH   8
#define DH    64
#define KV_W  (2 * KVH * DH)   // 1024

// ---------------- scratch (allocation-free: __device__ globals) ----------------
__device__ float g_Q[S_LEN * DM];        // 16 MB
__device__ float g_KV[S_LEN * KV_W];     //  8 MB
__device__ float g_attn[S_LEN * DM];     // 16 MB
__device__ float g_freq[32];             // rope frequency table

// ============================ helpers ====================================
__device__ __forceinline__ uint32_t f2tf32(float x) {
    uint32_t r;
    asm("cvt.rna.tf32.f32 %0, %1;" : "=r"(r) : "f"(x));
    return r;
}
__device__ __forceinline__ uint32_t smem_u32(const void* p) {
    uint32_t a;
    asm("{ .reg .u64 t; cvta.to.shared.u64 t, %1; cvt.u32.u64 %0, t; }" : "=r"(a) : "l"(p));
    return a;
}
#define CP_ASYNC16(dst, src) \
    asm volatile("cp.async.cg.shared.global [%0], [%1], 16;" :: "r"(dst), "l"(src))
#define CP_COMMIT() asm volatile("cp.async.commit_group;" ::: "memory")
#define CP_WAIT1()  asm volatile("cp.async.wait_group 1;" ::: "memory")

// D += A(16x8) * B(8x8), tf32 inputs, f32 accumulate (sm_80+ mma.sync).
__device__ __forceinline__ void mma_tf32(float* d,
                                         uint32_t a0, uint32_t a1, uint32_t a2, uint32_t a3,
                                         uint32_t b0, uint32_t b1) {
    asm volatile(
        "mma.sync.aligned.m16n8k8.row.col.f32.tf32.tf32.f32 "
        "{%0,%1,%2,%3}, {%4,%5,%6,%7}, {%8,%9}, {%0,%1,%2,%3};"
        : "+f"(d[0]), "+f"(d[1]), "+f"(d[2]), "+f"(d[3])
        : "r"(a0), "r"(a1), "r"(a2), "r"(a3), "r"(b0), "r"(b1));
}

// ==============================================================================
// 3xTF32 GEMM via mma.sync + cp.async: C[M,N] = A[M,K] @ B[N,K]^T + bias[N]
// 128x128 CTA tile, BK=16, 256 threads (8 warps, 64x32 warp tiles).
// smem: 3 stages of raw fp32 A[128][16]+B[128][16], row stride 20 (conflict-
// free & 16B-aligned for cp.async). tf32 hi/lo split done in registers.
// ==============================================================================
#define BK     16
#define SSTR   20
#define ST_F   (128 * SSTR)       // floats per tile
#define STG_F  (2 * ST_F)         // A+B per stage
#define NSTG   3
#define TG_SMEM (NSTG * STG_F * 4)  // 61440 B

__global__ __launch_bounds__(256, 2)
void tgemm_3xtf32_nt_bias(const float* __restrict__ A, const float* __restrict__ B,
                          const float* __restrict__ bias, float* __restrict__ C,
                          int M, int N, int K)
{
    extern __shared__ float sm[];
    const uint32_t smb = smem_u32(sm);

    const int tid  = threadIdx.x;
    const int wid  = tid >> 5;
    const int lane = tid & 31;
    const int qr   = lane >> 2;
    const int qc   = lane & 3;
    const int wm   = (wid & 1) * 64;
    const int wn   = (wid >> 1) * 32;
    const int brow = blockIdx.y * 128;
    const int bcol = blockIdx.x * 128;

    // loader mapping: thread owns tile row lr, 8 cols from lc
    const int lr = tid >> 1;
    const int lc = (tid & 1) * 8;
    const float* Ag = A + (size_t)(brow + lr) * K + lc;
    const float* Bg = B + (size_t)(bcol + lr) * K + lc;
    const uint32_t dst_off = (uint32_t)(lr * SSTR + lc) * 4;

    const int NT = K / BK;

    auto issue_stage = [&](int kt) {
        const uint32_t da = smb + (uint32_t)((kt % NSTG) * STG_F) * 4 + dst_off;
        const uint32_t db = da + ST_F * 4;
        const float* sa = Ag + kt * BK;
        const float* sb = Bg + kt * BK;
        CP_ASYNC16(da,      sa);
        CP_ASYNC16(da + 16, sa + 4);
        CP_ASYNC16(db,      sb);
        CP_ASYNC16(db + 16, sb + 4);
    };

    float acc[4][4][4];
#pragma unroll
    for (int mt = 0; mt < 4; mt++)
#pragma unroll
        for (int nt = 0; nt < 4; nt++)
#pragma unroll
            for (int i = 0; i < 4; i++) acc[mt][nt][i] = 0.0f;

    // prologue: 2 stages in flight
    issue_stage(0); CP_COMMIT();
    issue_stage(1); CP_COMMIT();

    for (int kt = 0; kt < NT; kt++) {
        CP_WAIT1();          // stage kt arrived
        __syncthreads();     // visible to all; slot (kt-1)%3 free for reuse

        if (kt + 2 < NT) issue_stage(kt + 2);
        CP_COMMIT();

        const float* As = sm + (kt % NSTG) * STG_F;
        const float* Bs = As + ST_F;

#pragma unroll
        for (int ks = 0; ks < 2; ks++) {
            // B fragments: convert fp32 -> tf32 hi/lo in registers
            uint32_t bh[4][2], bl[4][2];
#pragma unroll
            for (int nt = 0; nt < 4; nt++) {
                const int off = (wn + nt * 8 + qr) * SSTR + ks * 8 + qc;
                float f0 = Bs[off], f1 = Bs[off + 4];
                bh[nt][0] = f2tf32(f0);
                bh[nt][1] = f2tf32(f1);
                bl[nt][0] = f2tf32(f0 - __uint_as_float(bh[nt][0]));
                bl[nt][1] = f2tf32(f1 - __uint_as_float(bh[nt][1]));
            }
#pragma unroll
            for (int mt = 0; mt < 4; mt++) {
                const int off = (wm + mt * 16 + qr) * SSTR + ks * 8 + qc;
                float f0 = As[off];
                float f1 = As[off + 8 * SSTR];
                float f2 = As[off + 4];
                float f3 = As[off + 8 * SSTR + 4];
                uint32_t ah0 = f2tf32(f0), ah1 = f2tf32(f1);
                uint32_t ah2 = f2tf32(f2), ah3 = f2tf32(f3);
                uint32_t al0 = f2tf32(f0 - __uint_as_float(ah0));
                uint32_t al1 = f2tf32(f1 - __uint_as_float(ah1));
                uint32_t al2 = f2tf32(f2 - __uint_as_float(ah2));
                uint32_t al3 = f2tf32(f3 - __uint_as_float(ah3));
#pragma unroll
                for (int nt = 0; nt < 4; nt++) {
                    mma_tf32(acc[mt][nt], ah0, ah1, ah2, ah3, bh[nt][0], bh[nt][1]);
                    mma_tf32(acc[mt][nt], ah0, ah1, ah2, ah3, bl[nt][0], bl[nt][1]);
                    mma_tf32(acc[mt][nt], al0, al1, al2, al3, bh[nt][0], bh[nt][1]);
                }
            }
        }
        __syncthreads();   // done reading stage kt before loader overwrites slot
    }

#pragma unroll
    for (int mt = 0; mt < 4; mt++) {
        const int row = brow + wm + mt * 16 + qr;
#pragma unroll
        for (int nt = 0; nt < 4; nt++) {
            const int col = bcol + wn + nt * 8 + qc * 2;
            const float b0 = bias[col], b1 = bias[col + 1];
            *(float2*)(C + (size_t)row * N + col) =
                make_float2(acc[mt][nt][0] + b0, acc[mt][nt][1] + b1);
            *(float2*)(C + (size_t)(row + 8) * N + col) =
                make_float2(acc[mt][nt][2] + b0, acc[mt][nt][3] + b1);
        }
    }
}

// ==============================================================================
// RoPE
// ==============================================================================
__global__ void freq_kernel()
{
    int j = threadIdx.x;
    if (j < 32) g_freq[j] = (float)pow(10000.0, -(double)j / 32.0);
}

__global__ void rope_kernel(float* __restrict__ X, int H, int rowstride)
{
    int idx = blockIdx.x * blockDim.x + threadIdx.x;
    int total = S_LEN * H * (DH / 2);
    if (idx >= total) return;

    int j = idx & 31;
    int t = idx >> 5;
    int h = t % H;
    int s = t / H;

    float theta = (float)s * g_freq[j];
    float sn, cs;
    sincosf(theta, &sn, &cs);

    float* p = X + (size_t)s * rowstride + h * DH + 2 * j;
    float2 v = *(float2*)p;
    float2 o;
    o.x = v.x * cs - v.y * sn;
    o.y = v.x * sn + v.y * cs;
    *(float2*)p = o;
}

// ==============================================================================
// Flash attention on mma.sync tf32 with 3xTF32 compensation (unchanged, R5).
// ==============================================================================
#define FST   68
#define FBUF  (64 * FST)
#define FA_SMEM (5 * FBUF * 4)           // 87040 B

__global__ __launch_bounds__(128, 2)
void flash_attn_mma(const float* __restrict__ Q, const float* __restrict__ KV,
                    float* __restrict__ O)
{
    extern __shared__ float smf[];
    float* Qh = smf;
    float* Ql = smf + FBUF;
    float* Ks = smf + 2 * FBUF;
    float* Vs = smf + 3 * FBUF;
    float* Ps = smf + 4 * FBUF;

    const int qt   = blockIdx.x;
    const int h    = blockIdx.y;
    const int hk   = h >> 2;
    const int tid  = threadIdx.x;
    const int wid  = tid >> 5;
    const int lane = tid & 31;
    const int qr   = lane >> 2;
    const int qc   = lane & 3;
    const int wm   = wid * 16;

    {
        const float* src = Q + (size_t)(qt * 64) * DM + h * DH;
        for (int i = tid; i < 64 * 16; i += 128) {
            int r = i >> 4, c = (i & 15) << 2;
            float4 v = *(const float4*)(src + (size_t)r * DM + c);
            float f[4] = {v.x * 0.125f, v.y * 0.125f, v.z * 0.125f, v.w * 0.125f};
            uint32_t hh[4], ll[4];
#pragma unroll
            for (int j = 0; j < 4; j++) {
                hh[j] = f2tf32(f[j]);
                ll[j] = f2tf32(f[j] - __uint_as_float(hh[j]));
            }
            *(uint4*)&Qh[r * FST + c] = make_uint4(hh[0], hh[1], hh[2], hh[3]);
            *(uint4*)&Ql[r * FST + c] = make_uint4(ll[0], ll[1], ll[2], ll[3]);
        }
    }

    float m_i[2] = {-1e30f, -1e30f};
    float l_i[2] = {0.0f, 0.0f};
    float acc[8][4];
#pragma unroll
    for (int nt = 0; nt < 8; nt++)
#pragma unroll
        for (int i = 0; i < 4; i++) acc[nt][i] = 0.0f;

    for (int kt = 0; kt < 32; kt++) {
        __syncthreads();

        const float* ksrc = KV + (size_t)(kt * 64) * KV_W + hk * DH;
        const float* vsrc = ksrc + KVH * DH;
        for (int i = tid; i < 64 * 16; i += 128) {
            int r = i >> 4, c = (i & 15) << 2;
            *(float4*)(Ks + r * FST + c) = *(const float4*)(ksrc + (size_t)r * KV_W + c);
            *(float4*)(Vs + r * FST + c) = *(const float4*)(vsrc + (size_t)r * KV_W + c);
        }
        __syncthreads();

        float s[8][4];
#pragma unroll
        for (int nt = 0; nt < 8; nt++)
#pragma unroll
            for (int i = 0; i < 4; i++) s[nt][i] = 0.0f;

#pragma unroll
        for (int ks = 0; ks < 8; ks++) {
            const int aoff = (wm + qr) * FST + ks * 8 + qc;
            uint32_t qh0 = __float_as_uint(Qh[aoff]);
            uint32_t qh1 = __float_as_uint(Qh[aoff + 8 * FST]);
            uint32_t qh2 = __float_as_uint(Qh[aoff + 4]);
            uint32_t qh3 = __float_as_uint(Qh[aoff + 8 * FST + 4]);
            uint32_t ql0 = __float_as_uint(Ql[aoff]);
            uint32_t ql1 = __float_as_uint(Ql[aoff + 8 * FST]);
            uint32_t ql2 = __float_as_uint(Ql[aoff + 4]);
            uint32_t ql3 = __float_as_uint(Ql[aoff + 8 * FST + 4]);
#pragma unroll
            for (int nt = 0; nt < 8; nt++) {
                const int boff = (nt * 8 + qr) * FST + ks * 8 + qc;
                float f0 = Ks[boff], f1 = Ks[boff + 4];
                uint32_t kh0 = f2tf32(f0);
                uint32_t kh1 = f2tf32(f1);
                uint32_t kl0 = f2tf32(f0 - __uint_as_float(kh0));
                uint32_t kl1 = f2tf32(f1 - __uint_as_float(kh1));
                mma_tf32(s[nt], qh0, qh1, qh2, qh3, kh0, kh1);
                mma_tf32(s[nt], qh0, qh1, qh2, qh3, kl0, kl1);
                mma_tf32(s[nt], ql0, ql1, ql2, ql3, kh0, kh1);
            }
        }

#pragma unroll
        for (int half = 0; half < 2; half++) {
            float mt = -1e30f;
#pragma unroll
            for (int nt = 0; nt < 8; nt++)
                mt = fmaxf(mt, fmaxf(s[nt][2 * half], s[nt][2 * half + 1]));
            mt = fmaxf(mt, __shfl_xor_sync(0xffffffffu, mt, 1));
            mt = fmaxf(mt, __shfl_xor_sync(0xffffffffu, mt, 2));
            float m_new = fmaxf(m_i[half], mt);
            float alpha = __expf(m_i[half] - m_new);
            float rs = 0.0f;
#pragma unroll
            for (int nt = 0; nt < 8; nt++) {
                s[nt][2 * half]     = __expf(s[nt][2 * half] - m_new);
                s[nt][2 * half + 1] = __expf(s[nt][2 * half + 1] - m_new);
                rs += s[nt][2 * half] + s[nt][2 * half + 1];
            }
            rs += __shfl_xor_sync(0xffffffffu, rs, 1);
            rs += __shfl_xor_sync(0xffffffffu, rs, 2);
            l_i[half] = l_i[half] * alpha + rs;
            m_i[half] = m_new;
#pragma unroll
            for (int nt = 0; nt < 8; nt++) {
                acc[nt][2 * half]     *= alpha;
                acc[nt][2 * half + 1] *= alpha;
            }
        }

#pragma unroll
        for (int nt = 0; nt < 8; nt++) {
            *(float2*)&Ps[(wm + qr) * FST + nt * 8 + 2 * qc]     = make_float2(s[nt][0], s[nt][1]);
            *(float2*)&Ps[(wm + qr + 8) * FST + nt * 8 + 2 * qc] = make_float2(s[nt][2], s[nt][3]);
        }
        __syncwarp();

#pragma unroll
        for (int ks = 0; ks < 8; ks++) {
            const int poff = (wm + qr) * FST + ks * 8 + qc;
            float pf0 = Ps[poff];
            float pf1 = Ps[poff + 8 * FST];
            float pf2 = Ps[poff + 4];
            float pf3 = Ps[poff + 8 * FST + 4];
            uint32_t ph0 = f2tf32(pf0), ph1 = f2tf32(pf1);
            uint32_t ph2 = f2tf32(pf2), ph3 = f2tf32(pf3);
            uint32_t pl0 = f2tf32(pf0 - __uint_as_float(ph0));
            uint32_t pl1 = f2tf32(pf1 - __uint_as_float(ph1));
            uint32_t pl2 = f2tf32(pf2 - __uint_as_float(ph2));
            uint32_t pl3 = f2tf32(pf3 - __uint_as_float(ph3));
#pragma unroll
            for (int nt = 0; nt < 8; nt++) {
                float f0 = Vs[(ks * 8 + qc) * FST + nt * 8 + qr];
                float f1 = Vs[(ks * 8 + qc + 4) * FST + nt * 8 + qr];
                uint32_t vh0 = f2tf32(f0);
                uint32_t vh1 = f2tf32(f1);
                uint32_t vl0 = f2tf32(f0 - __uint_as_float(vh0));
                uint32_t vl1 = f2tf32(f1 - __uint_as_float(vh1));
                mma_tf32(acc[nt], ph0, ph1, ph2, ph3, vh0, vh1);
                mma_tf32(acc[nt], ph0, ph1, ph2, ph3, vl0, vl1);
                mma_tf32(acc[nt], pl0, pl1, pl2, pl3, vh0, vh1);
            }
        }
    }

    const float inv0 = 1.0f / l_i[0];
    const float inv1 = 1.0f / l_i[1];
    float* dst0 = O + (size_t)(qt * 64 + wm + qr) * DM + h * DH;
    float* dst1 = O + (size_t)(qt * 64 + wm + qr + 8) * DM + h * DH;
#pragma unroll
    for (int nt = 0; nt < 8; nt++) {
        *(float2*)(dst0 + nt * 8 + 2 * qc) = make_float2(acc[nt][0] * inv0, acc[nt][1] * inv0);
        *(float2*)(dst1 + nt * 8 + 2 * qc) = make_float2(acc[nt][2] * inv1, acc[nt][3] * inv1);
    }
}

// ==============================================================================
// launch
// ==============================================================================
extern "C" void kernel_launch(void* const* d_in, const int* in_sizes, int n_in,
                              void* d_out, int out_size)
{
    const float* x     = (const float*)d_in[0];
    const float* W_q   = (const float*)d_in[1];
    const float* b_q   = (const float*)d_in[2];
    const float* W_kv  = (const float*)d_in[3];
    const float* b_kv  = (const float*)d_in[4];
    const float* W_out = (const float*)d_in[5];
    const float* b_out = (const float*)d_in[6];
    float* out = (float*)d_out;

    float *qbuf, *kvbuf, *abuf;
    cudaGetSymbolAddress((void**)&qbuf, g_Q);
    cudaGetSymbolAddress((void**)&kvbuf, g_KV);
    cudaGetSymbolAddress((void**)&abuf, g_attn);

    cudaFuncSetAttribute(flash_attn_mma, cudaFuncAttributeMaxDynamicSharedMemorySize, FA_SMEM);
    cudaFuncSetAttribute(tgemm_3xtf32_nt_bias, cudaFuncAttributeMaxDynamicSharedMemorySize, TG_SMEM);

    freq_kernel<<<1, 32>>>();

    // Q projection: [2048,2048]
    tgemm_3xtf32_nt_bias<<<dim3(DM / 128, S_LEN / 128), 256, TG_SMEM>>>(
        x, W_q, b_q, qbuf, S_LEN, DM, DM);

    // KV projection: [2048,1024]
    tgemm_3xtf32_nt_bias<<<dim3(KV_W / 128, S_LEN / 128), 256, TG_SMEM>>>(
        x, W_kv, b_kv, kvbuf, S_LEN, KV_W, DM);

    // RoPE
    rope_kernel<<<(S_LEN * QH * (DH / 2) + 255) / 256, 256>>>(qbuf, QH, DM);
    rope_kernel<<<(S_LEN * KVH * (DH / 2) + 255) / 256, 256>>>(kvbuf, KVH, KV_W);

    // Flash attention (mma.sync tf32, 3x compensated)
    flash_attn_mma<<<dim3(S_LEN / 64, QH), 128, FA_SMEM>>>(qbuf, kvbuf, abuf);

    // Output projection: [2048,2048]
    tgemm_3xtf32_nt_bias<<<dim3(DM / 128, S_LEN / 128), 256, TG_SMEM>>>(
        abuf, W_out, b_out, out, S_LEN, DM, DM);
}

// round 8
// speedup vs baseline: 1.4124x; 1.4124x over previous
#include <cuda_runtime.h>
#include <math.h>
#include <stdint.h>

#define S_LEN 2048
#define DM    2048
#define QH    32
#define KVH   8
#define DH    64
#define KV_W  (2 * KVH * DH)   // 1024

// ---------------- scratch (allocation-free: __device__ globals) ----------------
__device__ float g_Q[S_LEN * DM];        // 16 MB
__device__ float g_KV[S_LEN * KV_W];     //  8 MB
__device__ float g_attn[S_LEN * DM];     // 16 MB
__device__ float g_freq[32];             // rope frequency table

// ============================ helpers ====================================
__device__ __forceinline__ uint32_t smem_u32(const void* p) {
    uint32_t a;
    asm("{ .reg .u64 t; cvta.to.shared.u64 t, %1; cvt.u32.u64 %0, t; }" : "=r"(a) : "l"(p));
    return a;
}
#define CP_ASYNC16(dst, src) \
    asm volatile("cp.async.cg.shared.global [%0], [%1], 16;" :: "r"(dst), "l"(src))
#define CP_COMMIT() asm volatile("cp.async.commit_group;" ::: "memory")
#define CP_WAIT1()  asm volatile("cp.async.wait_group 1;" ::: "memory")

// pack two floats into bf16x2: low half = f0, high half = f1
__device__ __forceinline__ uint32_t pack_bf16(float f1_hi, float f0_lo) {
    uint32_t d;
    asm("cvt.rn.bf16x2.f32 %0, %1, %2;" : "=r"(d) : "f"(f1_hi), "f"(f0_lo));
    return d;
}
// round-to-nearest hi/lo split of a pair: f = hi + lo, |lo| <= 2^-8 |f|
__device__ __forceinline__ void split2(float f0, float f1, uint32_t& h, uint32_t& l) {
    h = pack_bf16(f1, f0);
    float h0 = __uint_as_float(h << 16);
    float h1 = __uint_as_float(h & 0xFFFF0000u);
    l = pack_bf16(f1 - h1, f0 - h0);
}

// D += A(16x16) * B(16x8), bf16 inputs, f32 accumulate (sm_80+ mma.sync).
__device__ __forceinline__ void mma_bf16(float* d,
                                         uint32_t a0, uint32_t a1, uint32_t a2, uint32_t a3,
                                         uint32_t b0, uint32_t b1) {
    asm volatile(
        "mma.sync.aligned.m16n8k16.row.col.f32.bf16.bf16.f32 "
        "{%0,%1,%2,%3}, {%4,%5,%6,%7}, {%8,%9}, {%0,%1,%2,%3};"
        : "+f"(d[0]), "+f"(d[1]), "+f"(d[2]), "+f"(d[3])
        : "r"(a0), "r"(a1), "r"(a2), "r"(a3), "r"(b0), "r"(b1));
}

// ==============================================================================
// 3xBF16 GEMM via mma.sync + cp.async: C[M,N] = A[M,K] @ B[N,K]^T + bias[N]
// 128x128 CTA tile, BK=16, 128 threads (4 warps, 64x64 warp tiles).
// smem: 3 stages of raw fp32 A[128][16]+B[128][16], row stride 24 floats
// (conflict-free for float2 frag loads, 16B aligned for cp.async).
// bf16 hi/lo split done in registers; 3 MMAs: AhBh + AhBl + AlBh.
// ==============================================================================
#define BK     16
#define SSTR   24
#define ST_F   (128 * SSTR)       // 3072 floats per tile
#define STG_F  (2 * ST_F)         // A+B per stage
#define NSTG   3
#define TG_SMEM (NSTG * STG_F * 4)  // 73728 B

__global__ __launch_bounds__(128, 2)
void tgemm_bf16_nt_bias(const float* __restrict__ A, const float* __restrict__ B,
                        const float* __restrict__ bias, float* __restrict__ C,
                        int M, int N, int K)
{
    extern __shared__ float sm[];
    const uint32_t smb = smem_u32(sm);

    const int tid  = threadIdx.x;
    const int wid  = tid >> 5;
    const int lane = tid & 31;
    const int qr   = lane >> 2;
    const int qc   = lane & 3;
    const int wm   = (wid & 1) * 64;
    const int wn   = (wid >> 1) * 64;
    const int brow = blockIdx.y * 128;
    const int bcol = blockIdx.x * 128;

    // loader: thread owns one A row and one B row (16 floats each)
    const float* Ag = A + (size_t)(brow + tid) * K;
    const float* Bg = B + (size_t)(bcol + tid) * K;
    const uint32_t dst_off = (uint32_t)(tid * SSTR) * 4;

    const int NT = K / BK;

    auto issue_stage = [&](int kt) {
        const uint32_t da = smb + (uint32_t)((kt % NSTG) * STG_F) * 4 + dst_off;
        const uint32_t db = da + ST_F * 4;
        const float* sa = Ag + kt * BK;
        const float* sb = Bg + kt * BK;
#pragma unroll
        for (int j = 0; j < 4; j++) {
            CP_ASYNC16(da + 16 * j, sa + 4 * j);
            CP_ASYNC16(db + 16 * j, sb + 4 * j);
        }
    };

    float acc[4][8][4];
#pragma unroll
    for (int mt = 0; mt < 4; mt++)
#pragma unroll
        for (int nt = 0; nt < 8; nt++)
#pragma unroll
            for (int i = 0; i < 4; i++) acc[mt][nt][i] = 0.0f;

    issue_stage(0); CP_COMMIT();
    issue_stage(1); CP_COMMIT();

    for (int kt = 0; kt < NT; kt++) {
        CP_WAIT1();
        __syncthreads();

        if (kt + 2 < NT) issue_stage(kt + 2);
        CP_COMMIT();

        const float* As = sm + (kt % NSTG) * STG_F;
        const float* Bs = As + ST_F;

        // B fragments for 8 n-tiles: bf16 hi/lo in registers
        uint32_t bh[8][2], bl[8][2];
#pragma unroll
        for (int nt = 0; nt < 8; nt++) {
            const int off = (wn + nt * 8 + qr) * SSTR + 2 * qc;
            float2 f = *(const float2*)&Bs[off];
            float2 g = *(const float2*)&Bs[off + 8];
            split2(f.x, f.y, bh[nt][0], bl[nt][0]);
            split2(g.x, g.y, bh[nt][1], bl[nt][1]);
        }
#pragma unroll
        for (int mt = 0; mt < 4; mt++) {
            const int off = (wm + mt * 16 + qr) * SSTR + 2 * qc;
            float2 f0 = *(const float2*)&As[off];
            float2 f1 = *(const float2*)&As[off + 8 * SSTR];
            float2 f2 = *(const float2*)&As[off + 8];
            float2 f3 = *(const float2*)&As[off + 8 * SSTR + 8];
            uint32_t ah0, ah1, ah2, ah3, al0, al1, al2, al3;
            split2(f0.x, f0.y, ah0, al0);
            split2(f1.x, f1.y, ah1, al1);
            split2(f2.x, f2.y, ah2, al2);
            split2(f3.x, f3.y, ah3, al3);
#pragma unroll
            for (int nt = 0; nt < 8; nt++) {
                mma_bf16(acc[mt][nt], ah0, ah1, ah2, ah3, bh[nt][0], bh[nt][1]);
                mma_bf16(acc[mt][nt], ah0, ah1, ah2, ah3, bl[nt][0], bl[nt][1]);
                mma_bf16(acc[mt][nt], al0, al1, al2, al3, bh[nt][0], bh[nt][1]);
            }
        }
        __syncthreads();
    }

#pragma unroll
    for (int mt = 0; mt < 4; mt++) {
        const int row = brow + wm + mt * 16 + qr;
#pragma unroll
        for (int nt = 0; nt < 8; nt++) {
            const int col = bcol + wn + nt * 8 + qc * 2;
            const float b0 = bias[col], b1 = bias[col + 1];
            *(float2*)(C + (size_t)row * N + col) =
                make_float2(acc[mt][nt][0] + b0, acc[mt][nt][1] + b1);
            *(float2*)(C + (size_t)(row + 8) * N + col) =
                make_float2(acc[mt][nt][2] + b0, acc[mt][nt][3] + b1);
        }
    }
}

// ==============================================================================
// RoPE
// ==============================================================================
__global__ void freq_kernel()
{
    int j = threadIdx.x;
    if (j < 32) g_freq[j] = (float)pow(10000.0, -(double)j / 32.0);
}

__global__ void rope_kernel(float* __restrict__ X, int H, int rowstride)
{
    int idx = blockIdx.x * blockDim.x + threadIdx.x;
    int total = S_LEN * H * (DH / 2);
    if (idx >= total) return;

    int j = idx & 31;
    int t = idx >> 5;
    int h = t % H;
    int s = t / H;

    float theta = (float)s * g_freq[j];
    float sn, cs;
    sincosf(theta, &sn, &cs);

    float* p = X + (size_t)s * rowstride + h * DH + 2 * j;
    float2 v = *(float2*)p;
    float2 o;
    o.x = v.x * cs - v.y * sn;
    o.y = v.x * sn + v.y * cs;
    *(float2*)p = o;
}

// ==============================================================================
// Flash attention on bf16 3-term mma.sync.
// Block = (128 q-rows, head), 128 threads = 4 warps; warp owns 32 rows.
// Q, K, P stored in smem as packed bf16x2 {hi,lo} uint2; V raw fp32.
// ==============================================================================
#define QST 36        // uint2 stride for QHL/PHL rows
#define KST 36        // uint2 stride for KHL rows
#define VST 68        // float stride for Vs rows
#define OFF_PHL 36864                         // 128*36*8
#define OFF_KHL (OFF_PHL + 36864)             // 73728
#define OFF_VS  (OFF_KHL + 64 * KST * 8)      // 73728 + 18432 = 92160
#define FA_SMEM (OFF_VS + 64 * VST * 4)       // 92160 + 17408 = 109568

__global__ __launch_bounds__(128, 2)
void flash_attn_bf16(const float* __restrict__ Q, const float* __restrict__ KV,
                     float* __restrict__ O)
{
    extern __shared__ char smc[];
    uint2* QHL = (uint2*)smc;                 // [128][QST]
    uint2* PHL = (uint2*)(smc + OFF_PHL);     // [128][QST]
    uint2* KHL = (uint2*)(smc + OFF_KHL);     // [64][KST]
    float* Vs  = (float*)(smc + OFF_VS);      // [64][VST]

    const int qt   = blockIdx.x;
    const int h    = blockIdx.y;
    const int hk   = h >> 2;
    const int tid  = threadIdx.x;
    const int wid  = tid >> 5;
    const int lane = tid & 31;
    const int qr   = lane >> 2;
    const int qc   = lane & 3;
    const int wm   = wid * 32;      // warp's 32 q-rows

    // ---- Q fill: scale by 1/8, split hi/lo, pack ----
    {
        const float* src = Q + (size_t)(qt * 128 + tid) * DM + h * DH;
        uint2* dst = QHL + tid * QST;
#pragma unroll
        for (int j = 0; j < 16; j++) {
            float4 v = *(const float4*)(src + 4 * j);
            uint32_t h01, l01, h23, l23;
            split2(v.x * 0.125f, v.y * 0.125f, h01, l01);
            split2(v.z * 0.125f, v.w * 0.125f, h23, l23);
            *(uint4*)(dst + 2 * j) = make_uint4(h01, l01, h23, l23);
        }
    }

    float m_i[2][2], l_i[2][2];
#pragma unroll
    for (int mt = 0; mt < 2; mt++)
#pragma unroll
        for (int hf = 0; hf < 2; hf++) { m_i[mt][hf] = -1e30f; l_i[mt][hf] = 0.0f; }

    float acc[2][8][4];
#pragma unroll
    for (int mt = 0; mt < 2; mt++)
#pragma unroll
        for (int nt = 0; nt < 8; nt++)
#pragma unroll
            for (int i = 0; i < 4; i++) acc[mt][nt][i] = 0.0f;

    for (int kt = 0; kt < 32; kt++) {
        __syncthreads();   // all warps done with previous KHL/Vs

        // ---- K fill (packed bf16 hi/lo) + V fill (raw fp32) ----
        {
            const int row = tid >> 1;
            const int db  = (tid & 1) * 32;
            const float* ksrc = KV + (size_t)(kt * 64 + row) * KV_W + hk * DH + db;
            const float* vsrc = ksrc + KVH * DH;
            uint2* kd = KHL + row * KST + (db >> 1);
            float* vd = Vs + row * VST + db;
#pragma unroll
            for (int j = 0; j < 8; j++) {
                float4 v = *(const float4*)(ksrc + 4 * j);
                uint32_t h01, l01, h23, l23;
                split2(v.x, v.y, h01, l01);
                split2(v.z, v.w, h23, l23);
                *(uint4*)(kd + 2 * j) = make_uint4(h01, l01, h23, l23);
                *(float4*)(vd + 4 * j) = *(const float4*)(vsrc + 4 * j);
            }
        }
        __syncthreads();

        // ---- S = Q @ K^T (3xBF16) ----
        float s[2][8][4];
#pragma unroll
        for (int mt = 0; mt < 2; mt++)
#pragma unroll
            for (int nt = 0; nt < 8; nt++)
#pragma unroll
                for (int i = 0; i < 4; i++) s[mt][nt][i] = 0.0f;

#pragma unroll
        for (int ks = 0; ks < 4; ks++) {
            uint32_t bh[8][2], bl[8][2];
#pragma unroll
            for (int nt = 0; nt < 8; nt++) {
                const int kb = (nt * 8 + qr) * KST + ks * 8 + qc;
                uint2 t0 = KHL[kb];
                uint2 t1 = KHL[kb + 4];
                bh[nt][0] = t0.x; bl[nt][0] = t0.y;
                bh[nt][1] = t1.x; bl[nt][1] = t1.y;
            }
#pragma unroll
            for (int mt = 0; mt < 2; mt++) {
                const int qb = (wm + mt * 16 + qr) * QST + ks * 8 + qc;
                uint2 a0 = QHL[qb];
                uint2 a1 = QHL[qb + 8 * QST];
                uint2 a2 = QHL[qb + 4];
                uint2 a3 = QHL[qb + 8 * QST + 4];
#pragma unroll
                for (int nt = 0; nt < 8; nt++) {
                    mma_bf16(s[mt][nt], a0.x, a1.x, a2.x, a3.x, bh[nt][0], bh[nt][1]);
                    mma_bf16(s[mt][nt], a0.x, a1.x, a2.x, a3.x, bl[nt][0], bl[nt][1]);
                    mma_bf16(s[mt][nt], a0.y, a1.y, a2.y, a3.y, bh[nt][0], bh[nt][1]);
                }
            }
        }

        // ---- online softmax (rows qr, qr+8 per mt; quad reduction over qc) ----
#pragma unroll
        for (int mt = 0; mt < 2; mt++) {
#pragma unroll
            for (int hf = 0; hf < 2; hf++) {
                float mx = -1e30f;
#pragma unroll
                for (int nt = 0; nt < 8; nt++)
                    mx = fmaxf(mx, fmaxf(s[mt][nt][2 * hf], s[mt][nt][2 * hf + 1]));
                mx = fmaxf(mx, __shfl_xor_sync(0xffffffffu, mx, 1));
                mx = fmaxf(mx, __shfl_xor_sync(0xffffffffu, mx, 2));
                float m_new = fmaxf(m_i[mt][hf], mx);
                float alpha = __expf(m_i[mt][hf] - m_new);
                float rs = 0.0f;
#pragma unroll
                for (int nt = 0; nt < 8; nt++) {
                    s[mt][nt][2 * hf]     = __expf(s[mt][nt][2 * hf] - m_new);
                    s[mt][nt][2 * hf + 1] = __expf(s[mt][nt][2 * hf + 1] - m_new);
                    rs += s[mt][nt][2 * hf] + s[mt][nt][2 * hf + 1];
                }
                rs += __shfl_xor_sync(0xffffffffu, rs, 1);
                rs += __shfl_xor_sync(0xffffffffu, rs, 2);
                l_i[mt][hf] = l_i[mt][hf] * alpha + rs;
                m_i[mt][hf] = m_new;
#pragma unroll
                for (int nt = 0; nt < 8; nt++) {
                    acc[mt][nt][2 * hf]     *= alpha;
                    acc[mt][nt][2 * hf + 1] *= alpha;
                }
            }
        }

        // ---- write P packed (warp-private rows) ----
#pragma unroll
        for (int mt = 0; mt < 2; mt++) {
            const int r0 = (wm + mt * 16 + qr) * QST;
#pragma unroll
            for (int nt = 0; nt < 8; nt++) {
                uint32_t ph, pl;
                split2(s[mt][nt][0], s[mt][nt][1], ph, pl);
                PHL[r0 + nt * 4 + qc] = make_uint2(ph, pl);
                split2(s[mt][nt][2], s[mt][nt][3], ph, pl);
                PHL[r0 + 8 * QST + nt * 4 + qc] = make_uint2(ph, pl);
            }
        }
        __syncwarp();

        // ---- acc += P @ V (3xBF16); V converted in-loop from fp32 columns ----
#pragma unroll
        for (int ks = 0; ks < 4; ks++) {
            uint32_t vh[8][2], vl[8][2];
#pragma unroll
            for (int nt = 0; nt < 8; nt++) {
                const int n  = nt * 8 + qr;
                const int k0 = ks * 16 + 2 * qc;
                float f0 = Vs[k0 * VST + n];
                float f1 = Vs[(k0 + 1) * VST + n];
                split2(f0, f1, vh[nt][0], vl[nt][0]);
                float f2 = Vs[(k0 + 8) * VST + n];
                float f3 = Vs[(k0 + 9) * VST + n];
                split2(f2, f3, vh[nt][1], vl[nt][1]);
            }
#pragma unroll
            for (int mt = 0; mt < 2; mt++) {
                const int pb = (wm + mt * 16 + qr) * QST + ks * 8 + qc;
                uint2 p0 = PHL[pb];
                uint2 p1 = PHL[pb + 8 * QST];
                uint2 p2 = PHL[pb + 4];
                uint2 p3 = PHL[pb + 8 * QST + 4];
#pragma unroll
                for (int nt = 0; nt < 8; nt++) {
                    mma_bf16(acc[mt][nt], p0.x, p1.x, p2.x, p3.x, vh[nt][0], vh[nt][1]);
                    mma_bf16(acc[mt][nt], p0.x, p1.x, p2.x, p3.x, vl[nt][0], vl[nt][1]);
                    mma_bf16(acc[mt][nt], p0.y, p1.y, p2.y, p3.y, vh[nt][0], vh[nt][1]);
                }
            }
        }
    }

    // ---- epilogue: normalize, store ----
#pragma unroll
    for (int mt = 0; mt < 2; mt++) {
        const float i0 = 1.0f / l_i[mt][0];
        const float i1 = 1.0f / l_i[mt][1];
        float* d0 = O + (size_t)(qt * 128 + wm + mt * 16 + qr) * DM + h * DH;
        float* d1 = d0 + (size_t)8 * DM;
#pragma unroll
        for (int nt = 0; nt < 8; nt++) {
            *(float2*)(d0 + nt * 8 + 2 * qc) =
                make_float2(acc[mt][nt][0] * i0, acc[mt][nt][1] * i0);
            *(float2*)(d1 + nt * 8 + 2 * qc) =
                make_float2(acc[mt][nt][2] * i1, acc[mt][nt][3] * i1);
        }
    }
}

// ==============================================================================
// launch
// ==============================================================================
extern "C" void kernel_launch(void* const* d_in, const int* in_sizes, int n_in,
                              void* d_out, int out_size)
{
    const float* x     = (const float*)d_in[0];
    const float* W_q   = (const float*)d_in[1];
    const float* b_q   = (const float*)d_in[2];
    const float* W_kv  = (const float*)d_in[3];
    const float* b_kv  = (const float*)d_in[4];
    const float* W_out = (const float*)d_in[5];
    const float* b_out = (const float*)d_in[6];
    float* out = (float*)d_out;

    float *qbuf, *kvbuf, *abuf;
    cudaGetSymbolAddress((void**)&qbuf, g_Q);
    cudaGetSymbolAddress((void**)&kvbuf, g_KV);
    cudaGetSymbolAddress((void**)&abuf, g_attn);

    cudaFuncSetAttribute(flash_attn_bf16, cudaFuncAttributeMaxDynamicSharedMemorySize, FA_SMEM);
    cudaFuncSetAttribute(tgemm_bf16_nt_bias, cudaFuncAttributeMaxDynamicSharedMemorySize, TG_SMEM);

    freq_kernel<<<1, 32>>>();

    // Q projection: [2048,2048]
    tgemm_bf16_nt_bias<<<dim3(DM / 128, S_LEN / 128), 128, TG_SMEM>>>(
        x, W_q, b_q, qbuf, S_LEN, DM, DM);

    // KV projection: [2048,1024]
    tgemm_bf16_nt_bias<<<dim3(KV_W / 128, S_LEN / 128), 128, TG_SMEM>>>(
        x, W_kv, b_kv, kvbuf, S_LEN, KV_W, DM);

    // RoPE
    rope_kernel<<<(S_LEN * QH * (DH / 2) + 255) / 256, 256>>>(qbuf, QH, DM);
    rope_kernel<<<(S_LEN * KVH * (DH / 2) + 255) / 256, 256>>>(kvbuf, KVH, KV_W);

    // Flash attention (bf16 3-term mma.sync), 128 q-rows per block
    flash_attn_bf16<<<dim3(S_LEN / 128, QH), 128, FA_SMEM>>>(qbuf, kvbuf, abuf);

    // Output projection: [2048,2048]
    tgemm_bf16_nt_bias<<<dim3(DM / 128, S_LEN / 128), 128, TG_SMEM>>>(
        abuf, W_out, b_out, out, S_LEN, DM, DM);
}